// round 2
// baseline (speedup 1.0000x reference)
#include <cuda_runtime.h>

// Output: out[0, z, r, c, ch] = in[0, z_idx[z], row_idx[r], col_idx[c], 0]
// Shapes: in (1,128,128,128,32) f32; idx arrays 64 x int32; out (1,64,64,64,32) f32.
// One thread writes one float4 (4 channels). 8 threads per output voxel share
// one gathered scalar (L1 broadcast). Warp writes 512 contiguous bytes.

__global__ __launch_bounds__(256) void sd3d_kernel(
    const float* __restrict__ in,
    const int*   __restrict__ z_idx,
    const int*   __restrict__ row_idx,
    const int*   __restrict__ col_idx,
    float4*      __restrict__ out)
{
    int tid = blockIdx.x * blockDim.x + threadIdx.x;   // 0 .. 2,097,151
    int v = tid >> 3;          // output voxel index, 0 .. 64^3-1
    int c = v & 63;
    int r = (v >> 6) & 63;
    int z = v >> 12;

    int zz = __ldg(z_idx + z);
    int rr = __ldg(row_idx + r);
    int cc = __ldg(col_idx + c);

    // channel 0 of input voxel (zz, rr, cc); innermost stride 32 floats
    float val = __ldg(in + ((((long)zz * 128 + rr) * 128 + cc) << 5));

    out[tid] = make_float4(val, val, val, val);
}

extern "C" void kernel_launch(void* const* d_in, const int* in_sizes, int n_in,
                              void* d_out, int out_size)
{
    const float* in      = (const float*)d_in[0];
    const int*   z_idx   = (const int*)d_in[1];
    const int*   row_idx = (const int*)d_in[2];
    const int*   col_idx = (const int*)d_in[3];
    float4* out = (float4*)d_out;

    // out_size = 64*64*64*32 = 8,388,608 floats -> 2,097,152 float4 stores
    const int n_vec4 = 8388608 / 4;
    const int threads = 256;
    const int blocks = n_vec4 / threads;   // 8192
    sd3d_kernel<<<blocks, threads>>>(in, z_idx, row_idx, col_idx, out);
}